// round 9
// baseline (speedup 1.0000x reference)
#include <cuda_runtime.h>
#include <cuda_fp16.h>
#include <math.h>
#include <stdint.h>

// Problem constants
#define B_   8
#define N_   1024
#define F_   256
#define O_   256
#define H_   2
#define D_   4
#define ROWS (B_ * N_)       // 8192
#define KTOT 4096            // D_ * N_

// ---------------- scratch ---------------------------------------------------------
__device__ float   g_vsrc[D_ * F_];
__device__ float   g_vdst[D_ * F_];
__device__ float   g_esrc[D_ * B_ * N_];
__device__ float   g_edst[D_ * B_ * N_];
__device__ uint8_t g_bits[N_ * N_];
__device__ __half  g_Xh [ROWS * F_];            // fp16 X, 4 MB
__device__ __half  g_Wth[D_ * O_ * F_];         // [(d*256+o)][f] fp16
__device__ __half  g_P [ROWS * KTOT];           // [b*N+i][d*N+j]  67 MB
__device__ __half  g_Vt[B_ * O_ * KTOT];        // [b*O+o][d*N+j]  17 MB

__device__ __forceinline__ uint32_t smem_u32(const void* p) {
    uint32_t a;
    asm("{ .reg .u64 t; cvta.to.shared.u64 t, %1; cvt.u32.u64 %0, t; }" : "=r"(a) : "l"(p));
    return a;
}

#define LDSM_X4(r0, r1, r2, r3, addr) \
    asm volatile("ldmatrix.sync.aligned.m8n8.x4.shared.b16 {%0,%1,%2,%3}, [%4];" \
        : "=r"(r0), "=r"(r1), "=r"(r2), "=r"(r3) : "r"(addr))

#define MMA16816(c0, c1, c2, c3, a0, a1, a2, a3, b0, b1) \
    asm volatile("mma.sync.aligned.m16n8k16.row.col.f32.f16.f16.f32 " \
        "{%0,%1,%2,%3}, {%4,%5,%6,%7}, {%8,%9}, {%0,%1,%2,%3};" \
        : "+f"(c0), "+f"(c1), "+f"(c2), "+f"(c3) \
        : "r"(a0), "r"(a1), "r"(a2), "r"(a3), "r"(b0), "r"(b1))

__device__ __forceinline__ void cp16(uint32_t dst, const void* src) {
    asm volatile("cp.async.cg.shared.global [%0], [%1], 16;" :: "r"(dst), "l"(src));
}
#define CP_COMMIT() asm volatile("cp.async.commit_group;" ::: "memory")
#define CP_WAIT2()  asm volatile("cp.async.wait_group 2;" ::: "memory")

// ---------------- prepxh: fused prep2 (Wth + vsrc/vdst) and X->fp16 ---------------
// blocks 0..67: prep tasks (d = bx/17, task = bx%17); blocks 68..1091: xh
__global__ void __launch_bounds__(256) prepxh_kernel(const float* __restrict__ W,
                                                     const float* __restrict__ a,
                                                     const float* __restrict__ X) {
    const int bx = blockIdx.x;
    const int tid = threadIdx.x;

    if (bx >= 68) {
        int idx = (bx - 68) * 256 + tid;
        const float4* src = (const float4*)X + idx * 2;
        float4 v0 = src[0], v1 = src[1];
        __half2 h0 = __floats2half2_rn(v0.x, v0.y);
        __half2 h1 = __floats2half2_rn(v0.z, v0.w);
        __half2 h2 = __floats2half2_rn(v1.x, v1.y);
        __half2 h3 = __floats2half2_rn(v1.z, v1.w);
        uint4 pack;
        pack.x = *(uint32_t*)&h0; pack.y = *(uint32_t*)&h1;
        pack.z = *(uint32_t*)&h2; pack.w = *(uint32_t*)&h3;
        *((uint4*)g_Xh + idx) = pack;
        return;
    }

    const int d = bx / 17;
    const int task = bx % 17;
    const float* W0 = W + (size_t)(d * 2 + 0) * F_ * O_;
    const float* W1 = W + (size_t)(d * 2 + 1) * F_ * O_;

    if (task < 16) {
        const int fr = (task >> 2) * 64, oc = (task & 3) * 64;
        __shared__ float t[64][65];
#pragma unroll
        for (int p = 0; p < 16; p++) {
            int idx = p * 256 + tid;
            int o = idx & 63, f = idx >> 6;
            t[f][o] = W0[(size_t)(fr + f) * O_ + oc + o] + W1[(size_t)(fr + f) * O_ + oc + o];
        }
        __syncthreads();
#pragma unroll
        for (int p = 0; p < 16; p++) {
            int idx = p * 256 + tid;
            int f = idx & 63, o = idx >> 6;
            g_Wth[(size_t)(d * O_ + oc + o) * F_ + fr + f] = __float2half_rn(t[f][o]);
        }
    } else {
        __shared__ float sa[2 * O_];
        for (int i = tid; i < 2 * O_; i += 256)
            sa[i] = a[(d * 2 + 1) * (2 * O_) + i];
        __syncthreads();
        const int w = tid >> 5, lane = tid & 31;
        const float4* a1v = (const float4*)sa;
        const float4* a2v = (const float4*)(sa + O_);
        for (int r = 0; r < 32; r++) {
            int f = w * 32 + r;
            const float4* row = (const float4*)(W1 + (size_t)f * O_);
            float s1 = 0.f, s2 = 0.f;
#pragma unroll
            for (int q = 0; q < 2; q++) {
                float4 v = row[lane + q * 32];
                float4 x1 = a1v[lane + q * 32];
                float4 x2 = a2v[lane + q * 32];
                s1 += v.x * x1.x + v.y * x1.y + v.z * x1.z + v.w * x1.w;
                s2 += v.x * x2.x + v.y * x2.y + v.z * x2.z + v.w * x2.w;
            }
#pragma unroll
            for (int off = 16; off > 0; off >>= 1) {
                s1 += __shfl_down_sync(0xffffffffu, s1, off);
                s2 += __shfl_down_sync(0xffffffffu, s2, off);
            }
            if (lane == 0) {
                g_vsrc[d * F_ + f] = s1;
                g_vdst[d * F_ + f] = s2;
            }
        }
    }
}

// ---------------- e_src / e_dst + fused adjacency-bit packing ---------------------
__global__ void evec_kernel(const float* __restrict__ X,
                            const int* __restrict__ AU, const int* __restrict__ AD,
                            const int* __restrict__ AR, const int* __restrict__ AL) {
    int tid = threadIdx.x;

    {
        int idx4 = blockIdx.x * 256 + tid;
        int4 u = ((const int4*)AU)[idx4];
        int4 dd = ((const int4*)AD)[idx4];
        int4 r = ((const int4*)AR)[idx4];
        int4 l = ((const int4*)AL)[idx4];
        uint32_t pack = 0;
        pack |= ((u.x != 0) | ((dd.x != 0) << 1) | ((r.x != 0) << 2) | ((l.x != 0) << 3));
        pack |= ((u.y != 0) | ((dd.y != 0) << 1) | ((r.y != 0) << 2) | ((l.y != 0) << 3)) << 8;
        pack |= ((u.z != 0) | ((dd.z != 0) << 1) | ((r.z != 0) << 2) | ((l.z != 0) << 3)) << 16;
        pack |= ((u.w != 0) | ((dd.w != 0) << 1) | ((r.w != 0) << 2) | ((l.w != 0) << 3)) << 24;
        ((uint32_t*)g_bits)[idx4] = pack;
    }

    int w = tid >> 5, lane = tid & 31;
    int row = blockIdx.x * 8 + w;
    int b = row >> 10, n = row & (N_ - 1);

    float xv[8];
#pragma unroll
    for (int t = 0; t < 8; t++) xv[t] = X[(size_t)row * F_ + lane + t * 32];

#pragma unroll
    for (int d = 0; d < D_; d++) {
        float s1 = 0.f, s2 = 0.f;
#pragma unroll
        for (int t = 0; t < 8; t++) {
            s1 += xv[t] * g_vsrc[d * F_ + lane + t * 32];
            s2 += xv[t] * g_vdst[d * F_ + lane + t * 32];
        }
#pragma unroll
        for (int off = 16; off > 0; off >>= 1) {
            s1 += __shfl_down_sync(0xffffffffu, s1, off);
            s2 += __shfl_down_sync(0xffffffffu, s2, off);
        }
        if (lane == 0) {
            g_esrc[(d * B_ + b) * N_ + n] = s1;
            g_edst[(d * B_ + b) * N_ + n] = s2;
        }
    }
}

// ---------------- P build: softmax row -> fp16 P ----------------------------------
__global__ void __launch_bounds__(256) pbuild_kernel() {
    const int row = blockIdx.x;            // b*N + i
    const int b = row >> 10, i = row & (N_ - 1);
    const int tid = threadIdx.x;
    const int wid = tid >> 5, lane = tid & 31;
    const int j0 = tid * 4;

    __shared__ float red[8];
    __shared__ float bc[2];

    uint32_t bw = ((const uint32_t*)(g_bits + (size_t)i * N_))[tid];

    float es0 = g_esrc[(0 * B_ + b) * N_ + i];
    float es1 = g_esrc[(1 * B_ + b) * N_ + i];
    float es2 = g_esrc[(2 * B_ + b) * N_ + i];
    float es3 = g_esrc[(3 * B_ + b) * N_ + i];

    float4 ed0 = *(const float4*)(g_edst + (0 * B_ + b) * N_ + j0);
    float4 ed1 = *(const float4*)(g_edst + (1 * B_ + b) * N_ + j0);
    float4 ed2 = *(const float4*)(g_edst + (2 * B_ + b) * N_ + j0);
    float4 ed3 = *(const float4*)(g_edst + (3 * B_ + b) * N_ + j0);

    float e[4];
    unsigned byt[4];
#pragma unroll
    for (int q = 0; q < 4; q++) {
        unsigned bb8 = (bw >> (q * 8)) & 0xFF;
        byt[q] = bb8;
        float ev = -INFINITY;
        if (bb8) {
            int ds = 31 - __clz(bb8);
            float e0q = (q == 0) ? ed0.x : (q == 1) ? ed0.y : (q == 2) ? ed0.z : ed0.w;
            float e1q = (q == 0) ? ed1.x : (q == 1) ? ed1.y : (q == 2) ? ed1.z : ed1.w;
            float e2q = (q == 0) ? ed2.x : (q == 1) ? ed2.y : (q == 2) ? ed2.z : ed2.w;
            float e3q = (q == 0) ? ed3.x : (q == 1) ? ed3.y : (q == 2) ? ed3.z : ed3.w;
            float edv = (ds == 0) ? e0q : (ds == 1) ? e1q : (ds == 2) ? e2q : e3q;
            float esv = (ds == 0) ? es0 : (ds == 1) ? es1 : (ds == 2) ? es2 : es3;
            float s = esv + edv;
            ev = s > 0.f ? s : 0.01f * s;
        }
        e[q] = ev;
    }

    float m = fmaxf(fmaxf(e[0], e[1]), fmaxf(e[2], e[3]));
#pragma unroll
    for (int off = 16; off > 0; off >>= 1)
        m = fmaxf(m, __shfl_xor_sync(0xffffffffu, m, off));
    if (lane == 0) red[wid] = m;
    __syncthreads();
    if (tid == 0) {
        float mm = red[0];
#pragma unroll
        for (int k = 1; k < 8; k++) mm = fmaxf(mm, red[k]);
        bc[0] = mm;
    }
    __syncthreads();
    float rmax = bc[0];

    float wv[4], psum = 0.f;
#pragma unroll
    for (int q = 0; q < 4; q++) {
        wv[q] = __expf(e[q] - rmax);
        psum += wv[q];
    }
#pragma unroll
    for (int off = 16; off > 0; off >>= 1)
        psum += __shfl_xor_sync(0xffffffffu, psum, off);
    if (lane == 0) red[wid] = psum;
    __syncthreads();
    if (tid == 0) {
        float ss = 0.f;
#pragma unroll
        for (int k = 0; k < 8; k++) ss += red[k];
        bc[1] = 1.0f / (ss * (float)H_);
    }
    __syncthreads();
    float inv = bc[1];

    __half* Prow = g_P + (size_t)row * KTOT;
#pragma unroll
    for (int d = 0; d < D_; d++) {
        uint64_t pack = 0;
#pragma unroll
        for (int q = 0; q < 4; q++) {
            float v = (byt[q] >> d) & 1 ? wv[q] * inv : 0.f;
            pack |= (uint64_t)__half_as_ushort(__float2half_rn(v)) << (q * 16);
        }
        *(uint64_t*)(Prow + d * N_ + j0) = pack;
    }
}

// ---------------- shared HMMA tiling constants ------------------------------------
#define STRD 72
#define ABUF (128 * STRD)                 // halves per matrix buffer
#define HSM_GEMM (4 * ABUF * 2)           // 2-stage double buffer (gemm_whsum)
#define NSTG 4
#define HSM_MAIN (NSTG * 2 * ABUF * 2)    // 4-stage cp.async (maintc), 147456 B

// ---------------- HMMA GEMM: Vt = fp16( Xh @ Wth^T ), M=8192 N=1024 K=256 ---------
__global__ void __launch_bounds__(256, 1) gemm_whsum_kernel() {
    extern __shared__ __align__(16) __half hsm[];
    const int tid = threadIdx.x;
    const int wid = tid >> 5, lane = tid & 31;
    const int m0 = blockIdx.x * 128;
    const int n0 = blockIdx.y * 128;

    const int wm = wid & 3, wn = wid >> 2;
    const int gid = lane >> 2, tig = lane & 3;

    const __half* Abase = g_Xh  + (size_t)m0 * F_;
    const __half* Bbase = g_Wth + (size_t)n0 * F_;

    const int lrow = tid >> 3, lseg = tid & 7;

    float acc[2][8][4];
#pragma unroll
    for (int mt = 0; mt < 2; mt++)
#pragma unroll
        for (int nh = 0; nh < 8; nh++)
#pragma unroll
            for (int r = 0; r < 4; r++) acc[mt][nh][r] = 0.f;

    const uint32_t smem_base = smem_u32(hsm);
    const uint32_t a_lrow = lane & 15, a_lcol = (lane >> 4) * 8;
    const uint32_t b_lrow = (lane & 7) + ((lane >> 4) << 3), b_lcol = ((lane >> 3) & 1) * 8;

    uint4 pa[4], pb[4];
#pragma unroll
    for (int it = 0; it < 4; it++) {
        int row = lrow + it * 32;
        pa[it] = *(const uint4*)(Abase + (size_t)row * F_ + lseg * 8);
        pb[it] = *(const uint4*)(Bbase + (size_t)row * F_ + lseg * 8);
    }

    for (int c = 0; c < 4; c++) {
        const int s = c & 1;
        __half* As = hsm + s * (2 * ABUF);
        __half* Bs = As + ABUF;
#pragma unroll
        for (int it = 0; it < 4; it++) {
            int row = lrow + it * 32;
            *(uint4*)(As + row * STRD + lseg * 8) = pa[it];
            *(uint4*)(Bs + row * STRD + lseg * 8) = pb[it];
        }
        __syncthreads();

        if (c < 3) {
#pragma unroll
            for (int it = 0; it < 4; it++) {
                int row = lrow + it * 32;
                pa[it] = *(const uint4*)(Abase + (size_t)row * F_ + (c + 1) * 64 + lseg * 8);
                pb[it] = *(const uint4*)(Bbase + (size_t)row * F_ + (c + 1) * 64 + lseg * 8);
            }
        }

        const uint32_t As_b = smem_base + (uint32_t)(s * (2 * ABUF)) * 2;
        const uint32_t Bs_b = As_b + ABUF * 2;

#pragma unroll
        for (int ks = 0; ks < 4; ks++) {
            uint32_t af[2][4];
#pragma unroll
            for (int mt = 0; mt < 2; mt++) {
                uint32_t addr = As_b + ((wm * 32 + mt * 16 + a_lrow) * STRD + ks * 16 + a_lcol) * 2;
                LDSM_X4(af[mt][0], af[mt][1], af[mt][2], af[mt][3], addr);
            }
            uint32_t bf[4][4];
#pragma unroll
            for (int nt = 0; nt < 4; nt++) {
                uint32_t addr = Bs_b + ((wn * 64 + nt * 16 + b_lrow) * STRD + ks * 16 + b_lcol) * 2;
                LDSM_X4(bf[nt][0], bf[nt][1], bf[nt][2], bf[nt][3], addr);
            }
#pragma unroll
            for (int mt = 0; mt < 2; mt++)
#pragma unroll
                for (int nh = 0; nh < 8; nh++) {
                    const int nt = nh >> 1, hi = (nh & 1) * 2;
                    MMA16816(acc[mt][nh][0], acc[mt][nh][1], acc[mt][nh][2], acc[mt][nh][3],
                             af[mt][0], af[mt][1], af[mt][2], af[mt][3],
                             bf[nt][hi], bf[nt][hi + 1]);
                }
        }
        __syncthreads();
    }

    // epilogue: transpose via smem -> coalesced Vt[(b*256+o)][d*1024+j]
    __half* til = hsm;
#pragma unroll
    for (int mt = 0; mt < 2; mt++)
#pragma unroll
        for (int nh = 0; nh < 8; nh++) {
            int ml = wm * 32 + mt * 16 + gid;
            int cl = wn * 64 + nh * 8 + tig * 2;
            til[(cl + 0) * 136 + ml]     = __float2half_rn(acc[mt][nh][0]);
            til[(cl + 1) * 136 + ml]     = __float2half_rn(acc[mt][nh][1]);
            til[(cl + 0) * 136 + ml + 8] = __float2half_rn(acc[mt][nh][2]);
            til[(cl + 1) * 136 + ml + 8] = __float2half_rn(acc[mt][nh][3]);
        }
    __syncthreads();

    const int b  = m0 >> 10;
    const int j0 = m0 & (N_ - 1);
    const int d  = n0 >> 8;
    const int o0 = n0 & 255;
#pragma unroll
    for (int it = 0; it < 8; it++) {
        int q = tid * 8 + it;
        int ol = q >> 4, seg = q & 15;
        uint4 v = *(uint4*)(til + ol * 136 + seg * 8);
        *(uint4*)(g_Vt + (size_t)(b * O_ + o0 + ol) * KTOT + d * N_ + j0 + seg * 8) = v;
    }
}

// ---------------- main GEMM: 512 threads, warp grid 4x4, 4-stage cp.async ---------
__global__ void __launch_bounds__(512, 1) maintc_kernel(float* __restrict__ out) {
    extern __shared__ __align__(16) __half hsm[];
    const int tid = threadIdx.x;
    const int wid = tid >> 5, lane = tid & 31;
    const int m0 = blockIdx.x * 128;
    const int n0 = blockIdx.y * 128;
    const int b  = blockIdx.z;

    const int wm = wid & 3, wn = wid >> 2;       // 4 x 4 warp grid, warp tile 32x32
    const int gid = lane >> 2, tig = lane & 3;

    const __half* Pbase = g_P  + (size_t)(b * N_ + m0) * KTOT;
    const __half* Vbase = g_Vt + (size_t)(b * O_ + n0) * KTOT;

    const int lrow = tid >> 2;                   // 0..127 (one row per thread)
    const int lseg4 = tid & 3;                   // 2 segs per thread (it*4 + lseg4)

    float acc[2][4][4];
#pragma unroll
    for (int mt = 0; mt < 2; mt++)
#pragma unroll
        for (int nh = 0; nh < 4; nh++)
#pragma unroll
            for (int r = 0; r < 4; r++) acc[mt][nh][r] = 0.f;

    const uint32_t smem_base = smem_u32(hsm);
    const uint32_t a_lrow = lane & 15, a_lcol = (lane >> 4) * 8;
    const uint32_t b_lrow = (lane & 7) + ((lane >> 4) << 3), b_lcol = ((lane >> 3) & 1) * 8;

    // prefill stages 0..2
#pragma unroll
    for (int ps = 0; ps < 3; ps++) {
        uint32_t As = smem_base + (uint32_t)(ps * (2 * ABUF)) * 2;
        uint32_t Bs = As + ABUF * 2;
#pragma unroll
        for (int it = 0; it < 2; it++) {
            int seg = lseg4 + it * 4;
            uint32_t doff = (uint32_t)(lrow * STRD + seg * 8) * 2;
            cp16(As + doff, Pbase + (size_t)lrow * KTOT + ps * 64 + seg * 8);
            cp16(Bs + doff, Vbase + (size_t)lrow * KTOT + ps * 64 + seg * 8);
        }
        CP_COMMIT();
    }

    for (int c = 0; c < 64; c++) {
        CP_WAIT2();
        __syncthreads();

        const int s = c & 3;
        const uint32_t As_b = smem_base + (uint32_t)(s * (2 * ABUF)) * 2;
        const uint32_t Bs_b = As_b + ABUF * 2;

        if (c < 61) {
            const int nc = c + 3;
            uint32_t As = smem_base + (uint32_t)((nc & 3) * (2 * ABUF)) * 2;
            uint32_t Bs = As + ABUF * 2;
#pragma unroll
            for (int it = 0; it < 2; it++) {
                int seg = lseg4 + it * 4;
                uint32_t doff = (uint32_t)(lrow * STRD + seg * 8) * 2;
                cp16(As + doff, Pbase + (size_t)lrow * KTOT + nc * 64 + seg * 8);
                cp16(Bs + doff, Vbase + (size_t)lrow * KTOT + nc * 64 + seg * 8);
            }
        }
        CP_COMMIT();

#pragma unroll
        for (int ks = 0; ks < 4; ks++) {
            uint32_t af[2][4];
#pragma unroll
            for (int mt = 0; mt < 2; mt++) {
                uint32_t addr = As_b + ((wm * 32 + mt * 16 + a_lrow) * STRD + ks * 16 + a_lcol) * 2;
                LDSM_X4(af[mt][0], af[mt][1], af[mt][2], af[mt][3], addr);
            }
            uint32_t bf[2][4];
#pragma unroll
            for (int nt = 0; nt < 2; nt++) {
                uint32_t addr = Bs_b + ((wn * 32 + nt * 16 + b_lrow) * STRD + ks * 16 + b_lcol) * 2;
                LDSM_X4(bf[nt][0], bf[nt][1], bf[nt][2], bf[nt][3], addr);
            }
#pragma unroll
            for (int mt = 0; mt < 2; mt++)
#pragma unroll
                for (int nh = 0; nh < 4; nh++) {
                    const int nt = nh >> 1, hi = (nh & 1) * 2;
                    MMA16816(acc[mt][nh][0], acc[mt][nh][1], acc[mt][nh][2], acc[mt][nh][3],
                             af[mt][0], af[mt][1], af[mt][2], af[mt][3],
                             bf[nt][hi], bf[nt][hi + 1]);
                }
        }
        __syncthreads();
    }

#pragma unroll
    for (int mt = 0; mt < 2; mt++) {
#pragma unroll
        for (int nh = 0; nh < 4; nh++) {
            int row = m0 + wm * 32 + mt * 16 + gid;
            int col = n0 + wn * 32 + nh * 8 + tig * 2;
            float2 v0 = make_float2(acc[mt][nh][0], acc[mt][nh][1]);
            float2 v1 = make_float2(acc[mt][nh][2], acc[mt][nh][3]);
            *(float2*)(out + ((size_t)(b * N_ + row)) * O_ + col) = v0;
            *(float2*)(out + ((size_t)(b * N_ + row + 8)) * O_ + col) = v1;
        }
    }
}

// ---------------- launch: fork/join graph -----------------------------------------
extern "C" void kernel_launch(void* const* d_in, const int* in_sizes, int n_in,
                              void* d_out, int out_size) {
    const float* x  = (const float*)d_in[0];
    const int*   AU = (const int*)d_in[1];
    const int*   AD = (const int*)d_in[2];
    const int*   AR = (const int*)d_in[3];
    const int*   AL = (const int*)d_in[4];
    const float* W  = (const float*)d_in[5];
    const float* a  = (const float*)d_in[6];
    float* out = (float*)d_out;

    static cudaStream_t s2 = 0;
    static cudaEvent_t evFork = 0, evJoin = 0;
    if (!s2) {
        cudaStreamCreateWithFlags(&s2, cudaStreamNonBlocking);
        cudaEventCreateWithFlags(&evFork, cudaEventDisableTiming);
        cudaEventCreateWithFlags(&evJoin, cudaEventDisableTiming);
        cudaFuncSetAttribute(gemm_whsum_kernel, cudaFuncAttributeMaxDynamicSharedMemorySize, HSM_GEMM);
        cudaFuncSetAttribute(maintc_kernel, cudaFuncAttributeMaxDynamicSharedMemorySize, HSM_MAIN);
    }

    // head: fused prep + xh (both branches depend on it)           [launch #1]
    prepxh_kernel<<<68 + 1024, 256>>>(W, a, x);
    cudaEventRecord(evFork, 0);

    // side stream: gemm_whsum (produces Vt)                        [launch #2]
    cudaStreamWaitEvent(s2, evFork, 0);
    gemm_whsum_kernel<<<dim3(ROWS / 128, 1024 / 128), 256, HSM_GEMM, s2>>>();
    cudaEventRecord(evJoin, s2);

    // main stream: evec(+bits) -> pbuild (produces P)              [launch #3, #4]
    evec_kernel<<<ROWS / 8, 256>>>(x, AU, AD, AR, AL);
    pbuild_kernel<<<ROWS, 256>>>();

    // join, then the big GEMM                                      [launch #5]
    cudaStreamWaitEvent(0, evJoin, 0);
    maintc_kernel<<<dim3(N_ / 128, O_ / 128, B_), 512, HSM_MAIN>>>(out);
}

// round 10
// speedup vs baseline: 1.0416x; 1.0416x over previous
#include <cuda_runtime.h>
#include <cuda_fp16.h>
#include <math.h>
#include <stdint.h>

// Problem constants
#define B_   8
#define N_   1024
#define F_   256
#define O_   256
#define H_   2
#define D_   4
#define ROWS (B_ * N_)       // 8192
#define KTOT 4096            // D_ * N_

// ---------------- scratch ---------------------------------------------------------
__device__ float   g_vsrc[D_ * F_];
__device__ float   g_vdst[D_ * F_];
__device__ float   g_esrc[D_ * B_ * N_];
__device__ float   g_edst[D_ * B_ * N_];
__device__ uint8_t g_bits[N_ * N_];
__device__ __half  g_Xh [ROWS * F_];            // fp16 X, 4 MB
__device__ __half  g_Wth[D_ * O_ * F_];         // [(d*256+o)][f] fp16
__device__ __half  g_P [ROWS * KTOT];           // [b*N+i][d*N+j]  67 MB
__device__ __half  g_Vt[B_ * O_ * KTOT];        // [b*O+o][d*N+j]  17 MB

__device__ __forceinline__ uint32_t smem_u32(const void* p) {
    uint32_t a;
    asm("{ .reg .u64 t; cvta.to.shared.u64 t, %1; cvt.u32.u64 %0, t; }" : "=r"(a) : "l"(p));
    return a;
}

#define LDSM_X4(r0, r1, r2, r3, addr) \
    asm volatile("ldmatrix.sync.aligned.m8n8.x4.shared.b16 {%0,%1,%2,%3}, [%4];" \
        : "=r"(r0), "=r"(r1), "=r"(r2), "=r"(r3) : "r"(addr))

#define MMA16816(c0, c1, c2, c3, a0, a1, a2, a3, b0, b1) \
    asm volatile("mma.sync.aligned.m16n8k16.row.col.f32.f16.f16.f32 " \
        "{%0,%1,%2,%3}, {%4,%5,%6,%7}, {%8,%9}, {%0,%1,%2,%3};" \
        : "+f"(c0), "+f"(c1), "+f"(c2), "+f"(c3) \
        : "r"(a0), "r"(a1), "r"(a2), "r"(a3), "r"(b0), "r"(b1))

__device__ __forceinline__ void cp16(uint32_t dst, const void* src) {
    asm volatile("cp.async.cg.shared.global [%0], [%1], 16;" :: "r"(dst), "l"(src));
}
#define CP_COMMIT() asm volatile("cp.async.commit_group;" ::: "memory")
#define CP_WAIT2()  asm volatile("cp.async.wait_group 2;" ::: "memory")

// ---------------- prepxh: fused prep (Wth + vsrc/vdst) and X->fp16 ----------------
// blocks 0..67: prep tasks (d = bx/17, task = bx%17); blocks 68..1091: xh
__global__ void __launch_bounds__(256) prepxh_kernel(const float* __restrict__ W,
                                                     const float* __restrict__ a,
                                                     const float* __restrict__ X) {
    const int bx = blockIdx.x;
    const int tid = threadIdx.x;

    if (bx >= 68) {
        int idx = (bx - 68) * 256 + tid;
        const float4* src = (const float4*)X + idx * 2;
        float4 v0 = src[0], v1 = src[1];
        __half2 h0 = __floats2half2_rn(v0.x, v0.y);
        __half2 h1 = __floats2half2_rn(v0.z, v0.w);
        __half2 h2 = __floats2half2_rn(v1.x, v1.y);
        __half2 h3 = __floats2half2_rn(v1.z, v1.w);
        uint4 pack;
        pack.x = *(uint32_t*)&h0; pack.y = *(uint32_t*)&h1;
        pack.z = *(uint32_t*)&h2; pack.w = *(uint32_t*)&h3;
        *((uint4*)g_Xh + idx) = pack;
        return;
    }

    const int d = bx / 17;
    const int task = bx % 17;
    const float* W0 = W + (size_t)(d * 2 + 0) * F_ * O_;
    const float* W1 = W + (size_t)(d * 2 + 1) * F_ * O_;

    if (task < 16) {
        const int fr = (task >> 2) * 64, oc = (task & 3) * 64;
        __shared__ float t[64][65];
#pragma unroll
        for (int p = 0; p < 16; p++) {
            int idx = p * 256 + tid;
            int o = idx & 63, f = idx >> 6;
            t[f][o] = W0[(size_t)(fr + f) * O_ + oc + o] + W1[(size_t)(fr + f) * O_ + oc + o];
        }
        __syncthreads();
#pragma unroll
        for (int p = 0; p < 16; p++) {
            int idx = p * 256 + tid;
            int f = idx & 63, o = idx >> 6;
            g_Wth[(size_t)(d * O_ + oc + o) * F_ + fr + f] = __float2half_rn(t[f][o]);
        }
    } else {
        __shared__ float sa[2 * O_];
        for (int i = tid; i < 2 * O_; i += 256)
            sa[i] = a[(d * 2 + 1) * (2 * O_) + i];
        __syncthreads();
        const int w = tid >> 5, lane = tid & 31;
        const float4* a1v = (const float4*)sa;
        const float4* a2v = (const float4*)(sa + O_);
        for (int r = 0; r < 32; r++) {
            int f = w * 32 + r;
            const float4* row = (const float4*)(W1 + (size_t)f * O_);
            float s1 = 0.f, s2 = 0.f;
#pragma unroll
            for (int q = 0; q < 2; q++) {
                float4 v = row[lane + q * 32];
                float4 x1 = a1v[lane + q * 32];
                float4 x2 = a2v[lane + q * 32];
                s1 += v.x * x1.x + v.y * x1.y + v.z * x1.z + v.w * x1.w;
                s2 += v.x * x2.x + v.y * x2.y + v.z * x2.z + v.w * x2.w;
            }
#pragma unroll
            for (int off = 16; off > 0; off >>= 1) {
                s1 += __shfl_down_sync(0xffffffffu, s1, off);
                s2 += __shfl_down_sync(0xffffffffu, s2, off);
            }
            if (lane == 0) {
                g_vsrc[d * F_ + f] = s1;
                g_vdst[d * F_ + f] = s2;
            }
        }
    }
}

// ---------------- e_src / e_dst + fused adjacency-bit packing ---------------------
__global__ void evec_kernel(const float* __restrict__ X,
                            const int* __restrict__ AU, const int* __restrict__ AD,
                            const int* __restrict__ AR, const int* __restrict__ AL) {
    int tid = threadIdx.x;

    {
        int idx4 = blockIdx.x * 256 + tid;
        int4 u = ((const int4*)AU)[idx4];
        int4 dd = ((const int4*)AD)[idx4];
        int4 r = ((const int4*)AR)[idx4];
        int4 l = ((const int4*)AL)[idx4];
        uint32_t pack = 0;
        pack |= ((u.x != 0) | ((dd.x != 0) << 1) | ((r.x != 0) << 2) | ((l.x != 0) << 3));
        pack |= ((u.y != 0) | ((dd.y != 0) << 1) | ((r.y != 0) << 2) | ((l.y != 0) << 3)) << 8;
        pack |= ((u.z != 0) | ((dd.z != 0) << 1) | ((r.z != 0) << 2) | ((l.z != 0) << 3)) << 16;
        pack |= ((u.w != 0) | ((dd.w != 0) << 1) | ((r.w != 0) << 2) | ((l.w != 0) << 3)) << 24;
        ((uint32_t*)g_bits)[idx4] = pack;
    }

    int w = tid >> 5, lane = tid & 31;
    int row = blockIdx.x * 8 + w;
    int b = row >> 10, n = row & (N_ - 1);

    float xv[8];
#pragma unroll
    for (int t = 0; t < 8; t++) xv[t] = X[(size_t)row * F_ + lane + t * 32];

#pragma unroll
    for (int d = 0; d < D_; d++) {
        float s1 = 0.f, s2 = 0.f;
#pragma unroll
        for (int t = 0; t < 8; t++) {
            s1 += xv[t] * g_vsrc[d * F_ + lane + t * 32];
            s2 += xv[t] * g_vdst[d * F_ + lane + t * 32];
        }
#pragma unroll
        for (int off = 16; off > 0; off >>= 1) {
            s1 += __shfl_down_sync(0xffffffffu, s1, off);
            s2 += __shfl_down_sync(0xffffffffu, s2, off);
        }
        if (lane == 0) {
            g_esrc[(d * B_ + b) * N_ + n] = s1;
            g_edst[(d * B_ + b) * N_ + n] = s2;
        }
    }
}

// ---------------- P build: softmax row -> fp16 P (mask-based packing) -------------
__global__ void __launch_bounds__(256) pbuild_kernel() {
    const int row = blockIdx.x;            // b*N + i
    const int b = row >> 10, i = row & (N_ - 1);
    const int tid = threadIdx.x;
    const int wid = tid >> 5, lane = tid & 31;
    const int j0 = tid * 4;

    __shared__ float red[8];
    __shared__ float bc[2];

    uint32_t bw = ((const uint32_t*)(g_bits + (size_t)i * N_))[tid];

    float es0 = g_esrc[(0 * B_ + b) * N_ + i];
    float es1 = g_esrc[(1 * B_ + b) * N_ + i];
    float es2 = g_esrc[(2 * B_ + b) * N_ + i];
    float es3 = g_esrc[(3 * B_ + b) * N_ + i];

    float4 ed0 = *(const float4*)(g_edst + (0 * B_ + b) * N_ + j0);
    float4 ed1 = *(const float4*)(g_edst + (1 * B_ + b) * N_ + j0);
    float4 ed2 = *(const float4*)(g_edst + (2 * B_ + b) * N_ + j0);
    float4 ed3 = *(const float4*)(g_edst + (3 * B_ + b) * N_ + j0);

    float e[4];
    unsigned byt[4];
#pragma unroll
    for (int q = 0; q < 4; q++) {
        unsigned bb8 = (bw >> (q * 8)) & 0xFF;
        byt[q] = bb8;
        float ev = -INFINITY;
        if (bb8) {
            int ds = 31 - __clz(bb8);
            float e0q = (q == 0) ? ed0.x : (q == 1) ? ed0.y : (q == 2) ? ed0.z : ed0.w;
            float e1q = (q == 0) ? ed1.x : (q == 1) ? ed1.y : (q == 2) ? ed1.z : ed1.w;
            float e2q = (q == 0) ? ed2.x : (q == 1) ? ed2.y : (q == 2) ? ed2.z : ed2.w;
            float e3q = (q == 0) ? ed3.x : (q == 1) ? ed3.y : (q == 2) ? ed3.z : ed3.w;
            float edv = (ds == 0) ? e0q : (ds == 1) ? e1q : (ds == 2) ? e2q : e3q;
            float esv = (ds == 0) ? es0 : (ds == 1) ? es1 : (ds == 2) ? es2 : es3;
            float s = esv + edv;
            ev = s > 0.f ? s : 0.01f * s;
        }
        e[q] = ev;
    }

    float m = fmaxf(fmaxf(e[0], e[1]), fmaxf(e[2], e[3]));
#pragma unroll
    for (int off = 16; off > 0; off >>= 1)
        m = fmaxf(m, __shfl_xor_sync(0xffffffffu, m, off));
    if (lane == 0) red[wid] = m;
    __syncthreads();
    if (tid == 0) {
        float mm = red[0];
#pragma unroll
        for (int k = 1; k < 8; k++) mm = fmaxf(mm, red[k]);
        bc[0] = mm;
    }
    __syncthreads();
    float rmax = bc[0];

    float wv[4], psum = 0.f;
#pragma unroll
    for (int q = 0; q < 4; q++) {
        wv[q] = __expf(e[q] - rmax);
        psum += wv[q];
    }
#pragma unroll
    for (int off = 16; off > 0; off >>= 1)
        psum += __shfl_xor_sync(0xffffffffu, psum, off);
    if (lane == 0) red[wid] = psum;
    __syncthreads();
    if (tid == 0) {
        float ss = 0.f;
#pragma unroll
        for (int k = 0; k < 8; k++) ss += red[k];
        bc[1] = 1.0f / (ss * (float)H_);
    }
    __syncthreads();
    float inv = bc[1];

    // convert normalized weights once (2 packed cvts), mask per direction
    __half2 wh01 = __floats2half2_rn(wv[0] * inv, wv[1] * inv);
    __half2 wh23 = __floats2half2_rn(wv[2] * inv, wv[3] * inv);
    uint32_t w01 = *(uint32_t*)&wh01;
    uint32_t w23 = *(uint32_t*)&wh23;

    __half* Prow = g_P + (size_t)row * KTOT;
#pragma unroll
    for (int d = 0; d < D_; d++) {
        uint32_t m0 = ((-(int)((byt[0] >> d) & 1u)) & 0x0000FFFFu) |
                      ((-(int)((byt[1] >> d) & 1u)) & 0xFFFF0000u);
        uint32_t m1 = ((-(int)((byt[2] >> d) & 1u)) & 0x0000FFFFu) |
                      ((-(int)((byt[3] >> d) & 1u)) & 0xFFFF0000u);
        uint2 pack = make_uint2(w01 & m0, w23 & m1);
        *(uint2*)(Prow + d * N_ + j0) = pack;
    }
}

// ---------------- shared HMMA tiling constants ------------------------------------
#define STRD 72
#define ABUF (128 * STRD)                 // halves per matrix buffer
#define HSM_GEMM (4 * ABUF * 2)           // 2-stage double buffer (gemm_whsum)
#define NSTG 4
#define HSM_MAIN (NSTG * 2 * ABUF * 2)    // 4-stage cp.async (maintc), 147456 B

// ---------------- HMMA GEMM: Vt = fp16( Xh @ Wth^T ), M=8192 N=1024 K=256 ---------
__global__ void __launch_bounds__(256, 1) gemm_whsum_kernel() {
    extern __shared__ __align__(16) __half hsm[];
    const int tid = threadIdx.x;
    const int wid = tid >> 5, lane = tid & 31;
    const int m0 = blockIdx.x * 128;
    const int n0 = blockIdx.y * 128;

    const int wm = wid & 3, wn = wid >> 2;
    const int gid = lane >> 2, tig = lane & 3;

    const __half* Abase = g_Xh  + (size_t)m0 * F_;
    const __half* Bbase = g_Wth + (size_t)n0 * F_;

    const int lrow = tid >> 3, lseg = tid & 7;

    float acc[2][8][4];
#pragma unroll
    for (int mt = 0; mt < 2; mt++)
#pragma unroll
        for (int nh = 0; nh < 8; nh++)
#pragma unroll
            for (int r = 0; r < 4; r++) acc[mt][nh][r] = 0.f;

    const uint32_t smem_base = smem_u32(hsm);
    const uint32_t a_lrow = lane & 15, a_lcol = (lane >> 4) * 8;
    const uint32_t b_lrow = (lane & 7) + ((lane >> 4) << 3), b_lcol = ((lane >> 3) & 1) * 8;

    uint4 pa[4], pb[4];
#pragma unroll
    for (int it = 0; it < 4; it++) {
        int row = lrow + it * 32;
        pa[it] = *(const uint4*)(Abase + (size_t)row * F_ + lseg * 8);
        pb[it] = *(const uint4*)(Bbase + (size_t)row * F_ + lseg * 8);
    }

    for (int c = 0; c < 4; c++) {
        const int s = c & 1;
        __half* As = hsm + s * (2 * ABUF);
        __half* Bs = As + ABUF;
#pragma unroll
        for (int it = 0; it < 4; it++) {
            int row = lrow + it * 32;
            *(uint4*)(As + row * STRD + lseg * 8) = pa[it];
            *(uint4*)(Bs + row * STRD + lseg * 8) = pb[it];
        }
        __syncthreads();

        if (c < 3) {
#pragma unroll
            for (int it = 0; it < 4; it++) {
                int row = lrow + it * 32;
                pa[it] = *(const uint4*)(Abase + (size_t)row * F_ + (c + 1) * 64 + lseg * 8);
                pb[it] = *(const uint4*)(Bbase + (size_t)row * F_ + (c + 1) * 64 + lseg * 8);
            }
        }

        const uint32_t As_b = smem_base + (uint32_t)(s * (2 * ABUF)) * 2;
        const uint32_t Bs_b = As_b + ABUF * 2;

#pragma unroll
        for (int ks = 0; ks < 4; ks++) {
            uint32_t af[2][4];
#pragma unroll
            for (int mt = 0; mt < 2; mt++) {
                uint32_t addr = As_b + ((wm * 32 + mt * 16 + a_lrow) * STRD + ks * 16 + a_lcol) * 2;
                LDSM_X4(af[mt][0], af[mt][1], af[mt][2], af[mt][3], addr);
            }
            uint32_t bf[4][4];
#pragma unroll
            for (int nt = 0; nt < 4; nt++) {
                uint32_t addr = Bs_b + ((wn * 64 + nt * 16 + b_lrow) * STRD + ks * 16 + b_lcol) * 2;
                LDSM_X4(bf[nt][0], bf[nt][1], bf[nt][2], bf[nt][3], addr);
            }
#pragma unroll
            for (int mt = 0; mt < 2; mt++)
#pragma unroll
                for (int nh = 0; nh < 8; nh++) {
                    const int nt = nh >> 1, hi = (nh & 1) * 2;
                    MMA16816(acc[mt][nh][0], acc[mt][nh][1], acc[mt][nh][2], acc[mt][nh][3],
                             af[mt][0], af[mt][1], af[mt][2], af[mt][3],
                             bf[nt][hi], bf[nt][hi + 1]);
                }
        }
        __syncthreads();
    }

    // epilogue: transpose via smem -> coalesced Vt[(b*256+o)][d*1024+j]
    __half* til = hsm;
#pragma unroll
    for (int mt = 0; mt < 2; mt++)
#pragma unroll
        for (int nh = 0; nh < 8; nh++) {
            int ml = wm * 32 + mt * 16 + gid;
            int cl = wn * 64 + nh * 8 + tig * 2;
            til[(cl + 0) * 136 + ml]     = __float2half_rn(acc[mt][nh][0]);
            til[(cl + 1) * 136 + ml]     = __float2half_rn(acc[mt][nh][1]);
            til[(cl + 0) * 136 + ml + 8] = __float2half_rn(acc[mt][nh][2]);
            til[(cl + 1) * 136 + ml + 8] = __float2half_rn(acc[mt][nh][3]);
        }
    __syncthreads();

    const int b  = m0 >> 10;
    const int j0 = m0 & (N_ - 1);
    const int d  = n0 >> 8;
    const int o0 = n0 & 255;
#pragma unroll
    for (int it = 0; it < 8; it++) {
        int q = tid * 8 + it;
        int ol = q >> 4, seg = q & 15;
        uint4 v = *(uint4*)(til + ol * 136 + seg * 8);
        *(uint4*)(g_Vt + (size_t)(b * O_ + o0 + ol) * KTOT + d * N_ + j0 + seg * 8) = v;
    }
}

// ---------------- main GEMM: out[b] = P[b] @ Vt[b]^T, 256 thr, 4-stage cp.async ---
__global__ void __launch_bounds__(256, 1) maintc_kernel(float* __restrict__ out) {
    extern __shared__ __align__(16) __half hsm[];
    const int tid = threadIdx.x;
    const int wid = tid >> 5, lane = tid & 31;
    const int m0 = blockIdx.x * 128;
    const int n0 = blockIdx.y * 128;
    const int b  = blockIdx.z;

    const int wm = wid & 3, wn = wid >> 2;
    const int gid = lane >> 2, tig = lane & 3;

    const __half* Pbase = g_P  + (size_t)(b * N_ + m0) * KTOT;
    const __half* Vbase = g_Vt + (size_t)(b * O_ + n0) * KTOT;

    const int lrow = tid >> 3, lseg = tid & 7;

    float acc[2][8][4];
#pragma unroll
    for (int mt = 0; mt < 2; mt++)
#pragma unroll
        for (int nh = 0; nh < 8; nh++)
#pragma unroll
            for (int r = 0; r < 4; r++) acc[mt][nh][r] = 0.f;

    const uint32_t smem_base = smem_u32(hsm);
    const uint32_t a_lrow = lane & 15, a_lcol = (lane >> 4) * 8;
    const uint32_t b_lrow = (lane & 7) + ((lane >> 4) << 3), b_lcol = ((lane >> 3) & 1) * 8;

#pragma unroll
    for (int ps = 0; ps < 3; ps++) {
        uint32_t As = smem_base + (uint32_t)(ps * (2 * ABUF)) * 2;
        uint32_t Bs = As + ABUF * 2;
#pragma unroll
        for (int it = 0; it < 4; it++) {
            int row = lrow + it * 32;
            uint32_t doff = (uint32_t)(row * STRD + lseg * 8) * 2;
            cp16(As + doff, Pbase + (size_t)row * KTOT + ps * 64 + lseg * 8);
            cp16(Bs + doff, Vbase + (size_t)row * KTOT + ps * 64 + lseg * 8);
        }
        CP_COMMIT();
    }

    for (int c = 0; c < 64; c++) {
        CP_WAIT2();
        __syncthreads();

        const int s = c & 3;
        const uint32_t As_b = smem_base + (uint32_t)(s * (2 * ABUF)) * 2;
        const uint32_t Bs_b = As_b + ABUF * 2;

        if (c < 61) {
            const int nc = c + 3;
            uint32_t As = smem_base + (uint32_t)((nc & 3) * (2 * ABUF)) * 2;
            uint32_t Bs = As + ABUF * 2;
#pragma unroll
            for (int it = 0; it < 4; it++) {
                int row = lrow + it * 32;
                uint32_t doff = (uint32_t)(row * STRD + lseg * 8) * 2;
                cp16(As + doff, Pbase + (size_t)row * KTOT + nc * 64 + lseg * 8);
                cp16(Bs + doff, Vbase + (size_t)row * KTOT + nc * 64 + lseg * 8);
            }
        }
        CP_COMMIT();

#pragma unroll
        for (int ks = 0; ks < 4; ks++) {
            uint32_t af[2][4];
#pragma unroll
            for (int mt = 0; mt < 2; mt++) {
                uint32_t addr = As_b + ((wm * 32 + mt * 16 + a_lrow) * STRD + ks * 16 + a_lcol) * 2;
                LDSM_X4(af[mt][0], af[mt][1], af[mt][2], af[mt][3], addr);
            }
            uint32_t bf[4][4];
#pragma unroll
            for (int nt = 0; nt < 4; nt++) {
                uint32_t addr = Bs_b + ((wn * 64 + nt * 16 + b_lrow) * STRD + ks * 16 + b_lcol) * 2;
                LDSM_X4(bf[nt][0], bf[nt][1], bf[nt][2], bf[nt][3], addr);
            }
#pragma unroll
            for (int mt = 0; mt < 2; mt++)
#pragma unroll
                for (int nh = 0; nh < 8; nh++) {
                    const int nt = nh >> 1, hi = (nh & 1) * 2;
                    MMA16816(acc[mt][nh][0], acc[mt][nh][1], acc[mt][nh][2], acc[mt][nh][3],
                             af[mt][0], af[mt][1], af[mt][2], af[mt][3],
                             bf[nt][hi], bf[nt][hi + 1]);
                }
        }
        __syncthreads();
    }

#pragma unroll
    for (int mt = 0; mt < 2; mt++) {
#pragma unroll
        for (int nh = 0; nh < 8; nh++) {
            int row = m0 + wm * 32 + mt * 16 + gid;
            int col = n0 + wn * 64 + nh * 8 + tig * 2;
            float2 v0 = make_float2(acc[mt][nh][0], acc[mt][nh][1]);
            float2 v1 = make_float2(acc[mt][nh][2], acc[mt][nh][3]);
            *(float2*)(out + ((size_t)(b * N_ + row)) * O_ + col) = v0;
            *(float2*)(out + ((size_t)(b * N_ + row + 8)) * O_ + col) = v1;
        }
    }
}

// ---------------- launch: fork/join graph -----------------------------------------
extern "C" void kernel_launch(void* const* d_in, const int* in_sizes, int n_in,
                              void* d_out, int out_size) {
    const float* x  = (const float*)d_in[0];
    const int*   AU = (const int*)d_in[1];
    const int*   AD = (const int*)d_in[2];
    const int*   AR = (const int*)d_in[3];
    const int*   AL = (const int*)d_in[4];
    const float* W  = (const float*)d_in[5];
    const float* a  = (const float*)d_in[6];
    float* out = (float*)d_out;

    static cudaStream_t s2 = 0;
    static cudaEvent_t evFork = 0, evJoin = 0;
    if (!s2) {
        cudaStreamCreateWithFlags(&s2, cudaStreamNonBlocking);
        cudaEventCreateWithFlags(&evFork, cudaEventDisableTiming);
        cudaEventCreateWithFlags(&evJoin, cudaEventDisableTiming);
        cudaFuncSetAttribute(gemm_whsum_kernel, cudaFuncAttributeMaxDynamicSharedMemorySize, HSM_GEMM);
        cudaFuncSetAttribute(maintc_kernel, cudaFuncAttributeMaxDynamicSharedMemorySize, HSM_MAIN);
    }

    // head: fused prep + xh (both branches depend on it)           [launch #1]
    prepxh_kernel<<<68 + 1024, 256>>>(W, a, x);
    cudaEventRecord(evFork, 0);

    // side stream: gemm_whsum (produces Vt)                        [launch #2]
    cudaStreamWaitEvent(s2, evFork, 0);
    gemm_whsum_kernel<<<dim3(ROWS / 128, 1024 / 128), 256, HSM_GEMM, s2>>>();
    cudaEventRecord(evJoin, s2);

    // main stream: evec(+bits) -> pbuild (produces P)              [launch #3, #4]
    evec_kernel<<<ROWS / 8, 256>>>(x, AU, AD, AR, AL);
    pbuild_kernel<<<ROWS, 256>>>();

    // join, then the big GEMM                                      [launch #5]
    cudaStreamWaitEvent(0, evJoin, 0);
    maintc_kernel<<<dim3(N_ / 128, O_ / 128, B_), 256, HSM_MAIN>>>(out);
}